// round 13
// baseline (speedup 1.0000x reference)
#include <cuda_runtime.h>
#include <cuda_bf16.h>
#include <math.h>

#define NB  4
#define NT  256
#define NV  1024
#define NS  64
#define ND  1024
#define NCV 256
#define NCV2 288
#define NBT (NB*NT)

// ---------------- scratch (device globals; no allocs allowed) ----------------
__device__ __nv_bfloat16  g_Wu16[NCV*ND];
__device__ __nv_bfloat16  g_WkT16[ND*ND];     // Wk^T  (n,k) k-contiguous
__device__ __nv_bfloat16  g_WvT16[ND*ND];     // Wv^T
__device__ __nv_bfloat16  g_x16[NBT*ND];
__device__ __nv_bfloat16  g_vis16[NB*NV*NCV];
__device__ __nv_bfloat16  g_P1X16[NCV2*ND];   // rows 0..255 P1, row 256 rvec, 257..287 zero
__device__ __nv_bfloat16  g_P2T16[ND*NCV];    // P2^T (1024 rows, k=256) k-contig
__device__ __nv_bfloat16  g_G16[NBT*NCV];     // UNNORMALIZED Gu
__device__ float g_bo[ND];                    // bu @ Wv
__device__ float g_Zh[2][NBT*NCV2];           // Z split-K halves
__device__ float g_m[NBT], g_l[NBT];
__device__ unsigned g_mbits[NBT*32];          // bit-packed transposed mask
__device__ int   g_flags;

// ---------------- helpers ----------------
__device__ __forceinline__ void mma_bf16(float* c, const unsigned* a, const unsigned* b) {
    asm volatile(
        "mma.sync.aligned.m16n8k16.row.col.f32.bf16.bf16.f32 "
        "{%0,%1,%2,%3}, {%4,%5,%6,%7}, {%8,%9}, {%0,%1,%2,%3};"
        : "+f"(c[0]), "+f"(c[1]), "+f"(c[2]), "+f"(c[3])
        : "r"(a[0]), "r"(a[1]), "r"(a[2]), "r"(a[3]), "r"(b[0]), "r"(b[1]));
}
__device__ __forceinline__ void cp16(void* smem, const void* g) {
    unsigned s = (unsigned)__cvta_generic_to_shared(smem);
    asm volatile("cp.async.cg.shared.global [%0], [%1], 16;\n" :: "r"(s), "l"(g));
}
__device__ __forceinline__ void cp_commit() {
    asm volatile("cp.async.commit_group;\n");
}
__device__ __forceinline__ void cp_wait1() {
    asm volatile("cp.async.wait_group 1;\n");
}
__device__ __forceinline__ void st_bf16x4(__nv_bfloat16* p, float4 v) {
    __nv_bfloat162 lo = __floats2bfloat162_rn(v.x, v.y);
    __nv_bfloat162 hi = __floats2bfloat162_rn(v.z, v.w);
    uint2 u;
    u.x = *(unsigned*)&lo;
    u.y = *(unsigned*)&hi;
    *(uint2*)p = u;
}

// ---------------- fused prep: detect + rbo + convert + transpose-convert ----
__global__ __launch_bounds__(256) void prep_kernel(
        const float* __restrict__ Wu, const float* __restrict__ Wk,
        const float* __restrict__ Wv, const float* __restrict__ x,
        const float* __restrict__ vision, const float* __restrict__ bu,
        const unsigned* __restrict__ mask) {
    __shared__ float sh[32][33];
    int blk = blockIdx.x, tid = threadIdx.x;
    if (blk < 32) {                              // mask format detection
        int f = 0;
        for (int i = blk * 256 + tid; i < 32768; i += 32 * 256) {
            unsigned w = mask[i];
            if (w > 1u)           f |= 1;
            if (w == 0x3F800000u) f |= 2;
            if (w == 0x3F803F80u) f |= 4;
            if (w == 0x00003F80u) f |= 8;
        }
        if (f) atomicOr(&g_flags, f);
        return;
    }
    blk -= 32;
    if (blk < 32) {                              // rvec -> P1X row 256, bo = bu@Wv
        const float* W = (blk < 16) ? Wk : Wv;
        int jbase = (blk & 15) * 64;
        int jl = tid & 63, isl = tid >> 6;
        int j = jbase + jl;
        float s = 0.f;
        int i0 = isl * 256;
        #pragma unroll 8
        for (int i = 0; i < 256; i++) {
            int ii = i0 + i;
            s += bu[ii] * W[(size_t)ii * ND + j];
        }
        ((float*)sh)[tid] = s;
        __syncthreads();
        if (isl == 0) {
            float* r = (float*)sh;
            float tot = r[jl] + r[64 + jl] + r[128 + jl] + r[192 + jl];
            if (blk < 16) g_P1X16[(size_t)256 * ND + j] = __float2bfloat16(tot);
            else          g_bo[j] = tot;
        }
        return;
    }
    blk -= 32;
    if (blk < 256) {                             // Wu -> bf16
        int q = blk * 256 + tid;
        st_bf16x4(&g_Wu16[q * 4], ((const float4*)Wu)[q]);
        return;
    }
    blk -= 256;
    if (blk < 1024) {                            // x -> bf16
        int q = blk * 256 + tid;
        st_bf16x4(&g_x16[q * 4], ((const float4*)x)[q]);
        return;
    }
    blk -= 1024;
    if (blk < 1024) {                            // vision -> bf16
        int q = blk * 256 + tid;
        st_bf16x4(&g_vis16[q * 4], ((const float4*)vision)[q]);
        return;
    }
    blk -= 1024;
    {                                            // transpose-convert Wk / Wv
        int mat = blk >> 10;                     // 0 = Wk, 1 = Wv
        int tt = blk & 1023;
        int Tr = (tt >> 5) * 32, Tc = (tt & 31) * 32;
        const float* M = mat ? Wv : Wk;
        __nv_bfloat16* O = mat ? g_WvT16 : g_WkT16;
        int r = tid >> 5, c = tid & 31;
        #pragma unroll
        for (int i = 0; i < 4; i++)
            sh[r + 8 * i][c] = M[(size_t)(Tr + r + 8 * i) * ND + Tc + c];
        __syncthreads();
        int ci = tid >> 3, rp = (tid & 7) * 2;
        #pragma unroll
        for (int j = 0; j < 2; j++) {
            int ri = rp + 16 * j;
            __nv_bfloat162 p = __floats2bfloat162_rn(sh[ri][ci], sh[ri + 1][ci]);
            *(unsigned*)&O[(size_t)(Tc + ci) * ND + Tr + ri] = *(unsigned*)&p;
        }
    }
}

// ---------------- bf16 3-stage pipelined tensor GEMM (TRANSB layout) --------
// BM in {64,128}; 256 thr = 8 warps (2 x 4); warp tile (BM/2) x (BN/4).
// MODE 0: fused P GEMMs + bitpack, bf16 out.
//   bid<64:      P1X = A0@B0^T (M=256,N=1024), row=(bid>>5)*BM, col=(bid&31)*BN
//   64<=bid<128: P2T = A1@B1^T (M=1024,N=256), row=((bid-64)>>3)*BM, col*BN
//   bid>=128:    bitpack mask block (bid-128)
// MODE 1: split-K halves: z; Cp = C0 + z*csz (fp32)
// MODE 2: EPI with fused batch-softmax merge:
//         C = alpha[r]*acc + w[r]*bocol[c] + Xadd[r*ldc+c]
template <int BM, int BN, int MODE>
__global__ __launch_bounds__(256) void bgemm_kernel(
        const __nv_bfloat16* __restrict__ A0,
        const __nv_bfloat16* __restrict__ A1,
        const __nv_bfloat16* __restrict__ B0,
        const __nv_bfloat16* __restrict__ B1,
        void* __restrict__ C0, void* __restrict__ C1,
        int kiter, int lda, int ldb, int ldc, int csz,
        const float* __restrict__ mrow,
        const float* __restrict__ lrow,
        const float* __restrict__ bocol,
        const float* __restrict__ Xadd,
        const void* __restrict__ mraw) {
    constexpr int BK = 32, STR = 40;            // word-stride 20 -> conflict-free
    constexpr int WN = BN / 4, NI = (WN + 7) / 8;
    constexpr int MI = BM / 32;                 // 16-row tiles per warp
    __shared__ __nv_bfloat16 smA[3][BM * STR];
    __shared__ __nv_bfloat16 smB[3][BN * STR];
    __shared__ float red[(MODE == 2) ? 256 : 1];
    __shared__ float salpha[(MODE == 2) ? BM : 1];
    __shared__ float swv[(MODE == 2) ? BM : 1];

    int tid = threadIdx.x;

    const __nv_bfloat16* Ap = A0;
    const __nv_bfloat16* Bp = B0;
    void* Cp = C0;
    int row0, col0;
    if (MODE == 0) {
        int bid = blockIdx.x;
        if (bid >= 128) {                        // ---- bitpack branch ----
            int bb = bid - 128;
            int b = bb >> 5, vc = bb & 31;
            int flags = g_flags;
            int fmt = (flags & 12) ? 3 : (flags & 2) ? 2 : (flags & 1) ? 1 : 0;
            const size_t base = ((size_t)b * NV + vc * 32) * NT + tid;
            unsigned wd = 0;
            if (fmt == 0) {
                const int* p = (const int*)mraw;
                #pragma unroll
                for (int r = 0; r < 32; r++)
                    wd |= (p[base + (size_t)r * NT] != 0 ? 1u : 0u) << r;
            } else if (fmt == 1) {
                const unsigned char* p = (const unsigned char*)mraw;
                #pragma unroll
                for (int r = 0; r < 32; r++)
                    wd |= (p[base + (size_t)r * NT] != 0 ? 1u : 0u) << r;
            } else if (fmt == 2) {
                const float* p = (const float*)mraw;
                #pragma unroll
                for (int r = 0; r < 32; r++)
                    wd |= (p[base + (size_t)r * NT] != 0.0f ? 1u : 0u) << r;
            } else {
                const unsigned short* p = (const unsigned short*)mraw;
                #pragma unroll
                for (int r = 0; r < 32; r++)
                    wd |= (p[base + (size_t)r * NT] != 0 ? 1u : 0u) << r;
            }
            g_mbits[(b * NT + tid) * 32 + vc] = wd;
            return;
        }
        if (bid < 64) {
            row0 = (bid >> 5) * BM; col0 = (bid & 31) * BN;
        } else {
            Ap = A1; Bp = B1; Cp = C1;
            ldc = NCV;
            int t2 = bid - 64;
            row0 = (t2 >> 3) * BM; col0 = (t2 & 7) * BN;
        }
    } else {
        row0 = blockIdx.y * BM; col0 = blockIdx.x * BN;
        if (MODE == 1) {
            int kb = blockIdx.z * (kiter * BK);
            Ap = A0 + kb; Bp = B0 + kb;
            Cp = (float*)C0 + (size_t)blockIdx.z * csz;
        }
    }

    int warp = tid >> 5, lane = tid & 31;
    int wm = warp >> 2, wn = warp & 3;
    int g = lane >> 2, tg = lane & 3;

    float acc[MI][NI][4] = {};

    auto load_stage = [&](int s, int k0) {
        #pragma unroll
        for (int itr = 0; itr < BM / 64; itr++) {
            int e = itr * 256 + tid;
            int m = e >> 2, kq = e & 3;
            cp16(&smA[s][m * STR + kq * 8],
                 &Ap[(size_t)(row0 + m) * lda + k0 + kq * 8]);
        }
        if (BN == 64 || tid < 128) {
            int n = tid >> 2, kq = tid & 3;
            cp16(&smB[s][n * STR + kq * 8],
                 &Bp[(size_t)(col0 + n) * ldb + k0 + kq * 8]);
        }
        cp_commit();
    };

    load_stage(0, 0);
    load_stage(1, BK);

    // fused batch-softmax merge (MODE 2): overlaps with cp.async of stages 0/1
    if (MODE == 2) {
        int bb = row0 >> 8;                      // batch of all rows in tile
        float mv = mrow[bb * 256 + tid];
        red[tid] = mv;
        __syncthreads();
        for (int o = 128; o > 0; o >>= 1) {
            if (tid < o) red[tid] = fmaxf(red[tid], red[tid + o]);
            __syncthreads();
        }
        float M = red[0];
        __syncthreads();
        red[tid] = lrow[bb * 256 + tid] * expf(mv - M);
        __syncthreads();
        for (int o = 128; o > 0; o >>= 1) {
            if (tid < o) red[tid] += red[tid + o];
            __syncthreads();
        }
        float L = red[0];
        if (tid < BM) {
            float a_ = expf(mrow[row0 + tid] - M) / L;
            salpha[tid] = a_;
            swv[tid] = a_ * lrow[row0 + tid];
        }
        __syncthreads();
    }

    for (int it = 0; it < kiter; it++) {
        cp_wait1();
        __syncthreads();
        if (it + 2 < kiter) load_stage((it + 2) % 3, (it + 2) * BK);
        else                cp_commit();

        const __nv_bfloat16* As_ = smA[it % 3];
        const __nv_bfloat16* Bs_ = smB[it % 3];
        #pragma unroll
        for (int ks = 0; ks < BK; ks += 16) {
            unsigned a[MI][4];
            #pragma unroll
            for (int mi = 0; mi < MI; mi++) {
                int r = wm * (BM / 2) + mi * 16;
                a[mi][0] = *(const unsigned*)&As_[(r + g) * STR + ks + 2 * tg];
                a[mi][1] = *(const unsigned*)&As_[(r + 8 + g) * STR + ks + 2 * tg];
                a[mi][2] = *(const unsigned*)&As_[(r + g) * STR + ks + 8 + 2 * tg];
                a[mi][3] = *(const unsigned*)&As_[(r + 8 + g) * STR + ks + 8 + 2 * tg];
            }
            unsigned b[NI][2];
            #pragma unroll
            for (int ni = 0; ni < NI; ni++) {
                int c = wn * WN + ni * 8 + g;
                b[ni][0] = *(const unsigned*)&Bs_[c * STR + ks + 2 * tg];
                b[ni][1] = *(const unsigned*)&Bs_[c * STR + ks + 8 + 2 * tg];
            }
            #pragma unroll
            for (int mi = 0; mi < MI; mi++)
                #pragma unroll
                for (int ni = 0; ni < NI; ni++)
                    mma_bf16(acc[mi][ni], a[mi], b[ni]);
        }
        __syncthreads();
    }

    #pragma unroll
    for (int mi = 0; mi < MI; mi++) {
        #pragma unroll
        for (int ni = 0; ni < NI; ni++) {
            int r = row0 + wm * (BM / 2) + mi * 16 + g;
            int c = col0 + wn * WN + ni * 8 + tg * 2;
            float* a4 = acc[mi][ni];
            #pragma unroll
            for (int h = 0; h < 2; h++) {
                int rr = r + h * 8;
                float v0 = a4[h * 2], v1 = a4[h * 2 + 1];
                if (MODE == 0) {
                    __nv_bfloat162 p = __floats2bfloat162_rn(v0, v1);
                    *(unsigned*)&((__nv_bfloat16*)Cp)[(size_t)rr * ldc + c] =
                        *(unsigned*)&p;
                } else {
                    if (MODE == 2) {
                        float ar = salpha[rr - row0], wr = swv[rr - row0];
                        v0 = ar * v0 + wr * bocol[c]     + Xadd[(size_t)rr * ldc + c];
                        v1 = ar * v1 + wr * bocol[c + 1] + Xadd[(size_t)rr * ldc + c + 1];
                    }
                    ((float*)Cp)[(size_t)rr * ldc + c]     = v0;
                    ((float*)Cp)[(size_t)rr * ldc + c + 1] = v1;
                }
            }
        }
    }
}

// -- fused extract(bits) + qk + tensor-core gather ----------------------------
// svt[kp][col]: word = bf16 pair (V[2kp][col], V[2kp+1][col]); stride 264 words.
__global__ __launch_bounds__(256) void qkg_kernel() {
    int bt = blockIdx.x, b = bt / NT;
    __shared__ float zs[NCV];
    __shared__ float qks[NS];
    __shared__ unsigned es2[NS / 2];    // packed bf16 pairs of es
    __shared__ unsigned svt[32 * 264];  // 33.8 KB
    __shared__ float ms_sh, c0s;
    __shared__ int sidx[NS];
    int tid = threadIdx.x;
    int w = tid >> 5, lane = tid & 31;
    int g = lane >> 2, tg = lane & 3;

    // stage Z row (sum split-K halves) + c0
    {
        size_t o = (size_t)bt * NCV2 + tid;
        zs[tid] = g_Zh[0][o] + g_Zh[1][o];
        if (tid == 0) {
            size_t oc = (size_t)bt * NCV2 + 256;
            c0s = g_Zh[0][oc] + g_Zh[1][oc];
        }
    }

    // index extraction from bit-packed mask (warp 0)
    if (w == 0) {
        unsigned wd = g_mbits[bt * 32 + lane];
        int cnt = __popc(wd);
        int inc = cnt;
        #pragma unroll
        for (int o = 1; o < 32; o <<= 1) {
            int nv = __shfl_up_sync(0xFFFFFFFFu, inc, o);
            if (lane >= o) inc += nv;
        }
        int base = inc - cnt;
        int total = __shfl_sync(0xFFFFFFFFu, inc, 31);
        while (wd) {
            int bp = __ffs(wd) - 1;
            if (base < NS) sidx[base] = lane * 32 + bp;
            wd &= wd - 1;
            base++;
        }
        for (int s = total + lane; s < NS; s += 32) sidx[s] = NV;
    }
    __syncthreads();
    float c0 = c0s;

    // gather: stage vision row-pairs into svt (k-pair major), compute qk dots
    const __nv_bfloat16* vb = g_vis16 + (size_t)b * NV * NCV;
    #pragma unroll
    for (int qp = 0; qp < 4; qp++) {
        int se = w * 8 + 2 * qp;
        int ve = sidx[se], vo = sidx[se + 1];
        unsigned pe[4], po[4];
        float de = 0.f, dn = 0.f;
        if (ve < NV) {
            const __nv_bfloat16* vr = vb + (size_t)ve * NCV;
            #pragma unroll
            for (int i = 0; i < 4; i++) {
                int e = 2 * lane + 64 * i;
                pe[i] = *(const unsigned*)&vr[e];
                __nv_bfloat162 p2 = *(__nv_bfloat162*)&pe[i];
                de += __bfloat162float(p2.x) * zs[e]
                    + __bfloat162float(p2.y) * zs[e + 1];
            }
        } else { pe[0] = pe[1] = pe[2] = pe[3] = 0; }
        if (vo < NV) {
            const __nv_bfloat16* vr = vb + (size_t)vo * NCV;
            #pragma unroll
            for (int i = 0; i < 4; i++) {
                int e = 2 * lane + 64 * i;
                po[i] = *(const unsigned*)&vr[e];
                __nv_bfloat162 p2 = *(__nv_bfloat162*)&po[i];
                dn += __bfloat162float(p2.x) * zs[e]
                    + __bfloat162float(p2.y) * zs[e + 1];
            }
        } else { po[0] = po[1] = po[2] = po[3] = 0; }
        #pragma unroll
        for (int o = 16; o > 0; o >>= 1) {
            de += __shfl_down_sync(0xFFFFFFFFu, de, o);
            dn += __shfl_down_sync(0xFFFFFFFFu, dn, o);
        }
        if (lane == 0) {
            qks[se]     = (ve < NV) ? (de + c0) * (1.f / 32.f) - 100.f
                                    : c0 * (1.f / 32.f);
            qks[se + 1] = (vo < NV) ? (dn + c0) * (1.f / 32.f) - 100.f
                                    : c0 * (1.f / 32.f);
        }
        int kp = w * 4 + qp;
        #pragma unroll
        for (int i = 0; i < 4; i++) {
            unsigned w0 = __byte_perm(pe[i], po[i], 0x5410);
            unsigned w1 = __byte_perm(pe[i], po[i], 0x7632);
            *(uint2*)&svt[kp * 264 + 2 * lane + 64 * i] = make_uint2(w0, w1);
        }
    }
    __syncthreads();

    // per-token softmax stats + packed es (warp 0)
    if (w == 0) {
        float q1 = qks[lane], q2 = qks[lane + 32];
        float mx = fmaxf(q1, q2);
        #pragma unroll
        for (int o = 16; o > 0; o >>= 1)
            mx = fmaxf(mx, __shfl_xor_sync(0xFFFFFFFFu, mx, o));
        float l = expf(q1 - mx) + expf(q2 - mx);
        #pragma unroll
        for (int o = 16; o > 0; o >>= 1) l += __shfl_xor_sync(0xFFFFFFFFu, l, o);
        if (lane == 0) { g_m[bt] = mx; g_l[bt] = l; ms_sh = mx; }
        float m_ = __shfl_sync(0xFFFFFFFFu, mx, 0);
        float e0 = expf(qks[2 * lane] - m_);
        float e1 = expf(qks[2 * lane + 1] - m_);
        __nv_bfloat162 p = __floats2bfloat162_rn(e0, e1);
        es2[lane] = *(unsigned*)&p;
    }
    __syncthreads();

    // Gu = es @ V via tensor cores: warp handles 32 cols (n0 = w*32)
    {
        int n0 = w * 32;
        float d[4][4] = {};
        unsigned a[4];
        #pragma unroll
        for (int ks2 = 0; ks2 < 4; ks2++) {          // k-steps of 16 (kp base 8*ks2)
            int kp0 = ks2 * 8;
            unsigned ea0 = es2[(kp0 + tg) & 31];
            unsigned ea2 = es2[(kp0 + 4 + tg) & 31];
            a[0] = (lane < 4) ? ea0 : 0u;
            a[1] = 0u;
            a[2] = (lane < 4) ? ea2 : 0u;
            a[3] = 0u;
            #pragma unroll
            for (int nt = 0; nt < 4; nt++) {
                int n = n0 + nt * 8 + g;
                unsigned bfr[2];
                bfr[0] = svt[(kp0 + tg) * 264 + n];
                bfr[1] = svt[(kp0 + 4 + tg) * 264 + n];
                mma_bf16(d[nt], a, bfr);
            }
        }
        if (lane < 4) {
            #pragma unroll
            for (int nt = 0; nt < 4; nt++) {
                __nv_bfloat162 p = __floats2bfloat162_rn(d[nt][0], d[nt][1]);
                *(unsigned*)&g_G16[(size_t)bt * NCV + n0 + nt * 8 + 2 * tg] =
                    *(unsigned*)&p;
            }
        }
    }
}

// ---------------- launch ----------------
extern "C" void kernel_launch(void* const* d_in, const int* in_sizes, int n_in,
                              void* d_out, int out_size) {
    const float* x      = (const float*)d_in[0];
    const float* vision = (const float*)d_in[1];
    const void*  mask   = d_in[2];
    const float* Wu     = (const float*)d_in[3];
    const float* bu     = (const float*)d_in[4];
    const float* Wk     = (const float*)d_in[5];
    const float* Wv     = (const float*)d_in[6];
    float* out = (float*)d_out;

    float *Zh;
    cudaGetSymbolAddress((void**)&Zh, g_Zh);
    __nv_bfloat16 *Wu16, *WkT16, *WvT16, *x16, *P1X16, *P2T16, *G16;
    cudaGetSymbolAddress((void**)&Wu16, g_Wu16);
    cudaGetSymbolAddress((void**)&WkT16, g_WkT16);
    cudaGetSymbolAddress((void**)&WvT16, g_WvT16);
    cudaGetSymbolAddress((void**)&x16, g_x16);
    cudaGetSymbolAddress((void**)&P1X16, g_P1X16);
    cudaGetSymbolAddress((void**)&P2T16, g_P2T16);
    cudaGetSymbolAddress((void**)&G16, g_G16);
    float *bo, *mrow, *lrow;
    cudaGetSymbolAddress((void**)&bo, g_bo);
    cudaGetSymbolAddress((void**)&mrow, g_m);
    cudaGetSymbolAddress((void**)&lrow, g_l);

    // 1) fused prep: detect + rbo + conversions + W transposes
    prep_kernel<<<4416, 256>>>(Wu, Wk, Wv, x, vision, bu, (const unsigned*)mask);
    // 2) fused P GEMMs (BM=128: 64 + 64 blocks) + bitpack (128 blocks)
    bgemm_kernel<128, 32, 0><<<256, 256>>>(
        Wu16, WvT16, WkT16, Wu16, P1X16, P2T16,
        ND / 32, ND, ND, ND, 0, nullptr, nullptr, nullptr, nullptr, mask);
    // 3) Z halves: Z = X @ P1X^T, split-K=2, BM=128 -> 144 blocks (1 wave)
    bgemm_kernel<128, 32, 1><<<dim3(NCV2 / 32, NBT / 128, 2), 256>>>(
        x16, nullptr, P1X16, nullptr, Zh, nullptr,
        512 / 32, ND, ND, NCV2, NBT * NCV2, nullptr, nullptr, nullptr, nullptr,
        nullptr);
    // 4) fused extract + qk + tensor-core gather
    qkg_kernel<<<NBT, 256>>>();
    // 5) out = alpha*(Gu @ P2) + w*bo + x, BM=128 -> 128 blocks (1 wave)
    bgemm_kernel<128, 64, 2><<<dim3(ND / 64, NBT / 128, 1), 256>>>(
        G16, nullptr, P2T16, nullptr, out, nullptr,
        NCV / 32, NCV, NCV, ND, 0, mrow, lrow, bo, x, nullptr);
}

// round 14
// speedup vs baseline: 1.1287x; 1.1287x over previous
#include <cuda_runtime.h>
#include <cuda_bf16.h>
#include <math.h>

#define NB  4
#define NT  256
#define NV  1024
#define NS  64
#define ND  1024
#define NCV 256
#define NCV2 288
#define NBT (NB*NT)

// ---------------- scratch (device globals; no allocs allowed) ----------------
__device__ __nv_bfloat16  g_Wu16[NCV*ND];
__device__ __nv_bfloat16  g_WkT16[ND*ND];     // Wk^T  (n,k) k-contiguous
__device__ __nv_bfloat16  g_WvT16[ND*ND];     // Wv^T
__device__ __nv_bfloat16  g_x16[NBT*ND];
__device__ __nv_bfloat16  g_vis16[NB*NV*NCV];
__device__ __nv_bfloat16  g_P1X16[NCV2*ND];   // rows 0..255 P1, row 256 rvec, 257..287 zero
__device__ __nv_bfloat16  g_P2T16[ND*NCV];    // P2^T (1024 rows, k=256) k-contig
__device__ __nv_bfloat16  g_G16[NBT*NCV];     // UNNORMALIZED Gu
__device__ float g_bo[ND];                    // bu @ Wv
__device__ float g_Zh[2][NBT*NCV2];           // Z split-K halves
__device__ float g_m[NBT], g_l[NBT];
__device__ unsigned g_mbits[NBT*32];          // bit-packed transposed mask
__device__ int   g_flags;

// ---------------- helpers ----------------
__device__ __forceinline__ void mma_bf16(float* c, const unsigned* a, const unsigned* b) {
    asm volatile(
        "mma.sync.aligned.m16n8k16.row.col.f32.bf16.bf16.f32 "
        "{%0,%1,%2,%3}, {%4,%5,%6,%7}, {%8,%9}, {%0,%1,%2,%3};"
        : "+f"(c[0]), "+f"(c[1]), "+f"(c[2]), "+f"(c[3])
        : "r"(a[0]), "r"(a[1]), "r"(a[2]), "r"(a[3]), "r"(b[0]), "r"(b[1]));
}
__device__ __forceinline__ void ldsm_x2_t(unsigned& r0, unsigned& r1, unsigned addr) {
    asm volatile("ldmatrix.sync.aligned.m8n8.x2.trans.shared.b16 {%0,%1}, [%2];"
                 : "=r"(r0), "=r"(r1) : "r"(addr));
}
__device__ __forceinline__ void cp16(void* smem, const void* g) {
    unsigned s = (unsigned)__cvta_generic_to_shared(smem);
    asm volatile("cp.async.cg.shared.global [%0], [%1], 16;\n" :: "r"(s), "l"(g));
}
__device__ __forceinline__ void cp_commit() {
    asm volatile("cp.async.commit_group;\n");
}
__device__ __forceinline__ void cp_wait1() {
    asm volatile("cp.async.wait_group 1;\n");
}
__device__ __forceinline__ void cp_wait0() {
    asm volatile("cp.async.wait_group 0;\n");
}
__device__ __forceinline__ void st_bf16x4(__nv_bfloat16* p, float4 v) {
    __nv_bfloat162 lo = __floats2bfloat162_rn(v.x, v.y);
    __nv_bfloat162 hi = __floats2bfloat162_rn(v.z, v.w);
    uint2 u;
    u.x = *(unsigned*)&lo;
    u.y = *(unsigned*)&hi;
    *(uint2*)p = u;
}

// ---------------- fused prep: detect + rbo + convert + transpose-convert ----
__global__ __launch_bounds__(256) void prep_kernel(
        const float* __restrict__ Wu, const float* __restrict__ Wk,
        const float* __restrict__ Wv, const float* __restrict__ x,
        const float* __restrict__ vision, const float* __restrict__ bu,
        const unsigned* __restrict__ mask) {
    __shared__ float sh[32][33];
    int blk = blockIdx.x, tid = threadIdx.x;
    if (blk < 32) {                              // mask format detection
        int f = 0;
        for (int i = blk * 256 + tid; i < 32768; i += 32 * 256) {
            unsigned w = mask[i];
            if (w > 1u)           f |= 1;
            if (w == 0x3F800000u) f |= 2;
            if (w == 0x3F803F80u) f |= 4;
            if (w == 0x00003F80u) f |= 8;
        }
        if (f) atomicOr(&g_flags, f);
        return;
    }
    blk -= 32;
    if (blk < 32) {                              // rvec -> P1X row 256, bo = bu@Wv
        const float* W = (blk < 16) ? Wk : Wv;
        int jbase = (blk & 15) * 64;
        int jl = tid & 63, isl = tid >> 6;
        int j = jbase + jl;
        float s = 0.f;
        int i0 = isl * 256;
        #pragma unroll 8
        for (int i = 0; i < 256; i++) {
            int ii = i0 + i;
            s += bu[ii] * W[(size_t)ii * ND + j];
        }
        ((float*)sh)[tid] = s;
        __syncthreads();
        if (isl == 0) {
            float* r = (float*)sh;
            float tot = r[jl] + r[64 + jl] + r[128 + jl] + r[192 + jl];
            if (blk < 16) g_P1X16[(size_t)256 * ND + j] = __float2bfloat16(tot);
            else          g_bo[j] = tot;
        }
        return;
    }
    blk -= 32;
    if (blk < 256) {                             // Wu -> bf16
        int q = blk * 256 + tid;
        st_bf16x4(&g_Wu16[q * 4], ((const float4*)Wu)[q]);
        return;
    }
    blk -= 256;
    if (blk < 1024) {                            // x -> bf16
        int q = blk * 256 + tid;
        st_bf16x4(&g_x16[q * 4], ((const float4*)x)[q]);
        return;
    }
    blk -= 1024;
    if (blk < 1024) {                            // vision -> bf16
        int q = blk * 256 + tid;
        st_bf16x4(&g_vis16[q * 4], ((const float4*)vision)[q]);
        return;
    }
    blk -= 1024;
    {                                            // transpose-convert Wk / Wv
        int mat = blk >> 10;                     // 0 = Wk, 1 = Wv
        int tt = blk & 1023;
        int Tr = (tt >> 5) * 32, Tc = (tt & 31) * 32;
        const float* M = mat ? Wv : Wk;
        __nv_bfloat16* O = mat ? g_WvT16 : g_WkT16;
        int r = tid >> 5, c = tid & 31;
        #pragma unroll
        for (int i = 0; i < 4; i++)
            sh[r + 8 * i][c] = M[(size_t)(Tr + r + 8 * i) * ND + Tc + c];
        __syncthreads();
        int ci = tid >> 3, rp = (tid & 7) * 2;
        #pragma unroll
        for (int j = 0; j < 2; j++) {
            int ri = rp + 16 * j;
            __nv_bfloat162 p = __floats2bfloat162_rn(sh[ri][ci], sh[ri + 1][ci]);
            *(unsigned*)&O[(size_t)(Tc + ci) * ND + Tr + ri] = *(unsigned*)&p;
        }
    }
}

// ---------------- bf16 3-stage pipelined tensor GEMM (TRANSB layout) --------
// MODE 0: fused P GEMMs + bitpack (bid>=128), bf16 out
// MODE 1: split-K halves: z; Cp = C0 + z*csz (fp32)
// MODE 2: EPI with fused batch-softmax merge
template <int BM, int BN, int MODE>
__global__ __launch_bounds__(256) void bgemm_kernel(
        const __nv_bfloat16* __restrict__ A0,
        const __nv_bfloat16* __restrict__ A1,
        const __nv_bfloat16* __restrict__ B0,
        const __nv_bfloat16* __restrict__ B1,
        void* __restrict__ C0, void* __restrict__ C1,
        int kiter, int lda, int ldb, int ldc, int csz,
        const float* __restrict__ mrow,
        const float* __restrict__ lrow,
        const float* __restrict__ bocol,
        const float* __restrict__ Xadd,
        const void* __restrict__ mraw) {
    constexpr int BK = 32, STR = 40;
    constexpr int WN = BN / 4, NI = (WN + 7) / 8;
    constexpr int MI = BM / 32;
    __shared__ __nv_bfloat16 smA[3][BM * STR];
    __shared__ __nv_bfloat16 smB[3][BN * STR];
    __shared__ float red[(MODE == 2) ? 256 : 1];
    __shared__ float salpha[(MODE == 2) ? BM : 1];
    __shared__ float swv[(MODE == 2) ? BM : 1];

    int tid = threadIdx.x;

    const __nv_bfloat16* Ap = A0;
    const __nv_bfloat16* Bp = B0;
    void* Cp = C0;
    int row0, col0;
    if (MODE == 0) {
        int bid = blockIdx.x;
        if (bid >= 128) {                        // ---- bitpack branch ----
            int bb = bid - 128;
            int b = bb >> 5, vc = bb & 31;
            int flags = g_flags;
            int fmt = (flags & 12) ? 3 : (flags & 2) ? 2 : (flags & 1) ? 1 : 0;
            const size_t base = ((size_t)b * NV + vc * 32) * NT + tid;
            unsigned wd = 0;
            if (fmt == 0) {
                const int* p = (const int*)mraw;
                #pragma unroll
                for (int r = 0; r < 32; r++)
                    wd |= (p[base + (size_t)r * NT] != 0 ? 1u : 0u) << r;
            } else if (fmt == 1) {
                const unsigned char* p = (const unsigned char*)mraw;
                #pragma unroll
                for (int r = 0; r < 32; r++)
                    wd |= (p[base + (size_t)r * NT] != 0 ? 1u : 0u) << r;
            } else if (fmt == 2) {
                const float* p = (const float*)mraw;
                #pragma unroll
                for (int r = 0; r < 32; r++)
                    wd |= (p[base + (size_t)r * NT] != 0.0f ? 1u : 0u) << r;
            } else {
                const unsigned short* p = (const unsigned short*)mraw;
                #pragma unroll
                for (int r = 0; r < 32; r++)
                    wd |= (p[base + (size_t)r * NT] != 0 ? 1u : 0u) << r;
            }
            g_mbits[(b * NT + tid) * 32 + vc] = wd;
            return;
        }
        if (bid < 64) {
            row0 = (bid >> 5) * BM; col0 = (bid & 31) * BN;
        } else {
            Ap = A1; Bp = B1; Cp = C1;
            ldc = NCV;
            int t2 = bid - 64;
            row0 = (t2 >> 3) * BM; col0 = (t2 & 7) * BN;
        }
    } else {
        row0 = blockIdx.y * BM; col0 = blockIdx.x * BN;
        if (MODE == 1) {
            int kb = blockIdx.z * (kiter * BK);
            Ap = A0 + kb; Bp = B0 + kb;
            Cp = (float*)C0 + (size_t)blockIdx.z * csz;
        }
    }

    int warp = tid >> 5, lane = tid & 31;
    int wm = warp >> 2, wn = warp & 3;
    int g = lane >> 2, tg = lane & 3;

    float acc[MI][NI][4] = {};

    auto load_stage = [&](int s, int k0) {
        #pragma unroll
        for (int itr = 0; itr < BM / 64; itr++) {
            int e = itr * 256 + tid;
            int m = e >> 2, kq = e & 3;
            cp16(&smA[s][m * STR + kq * 8],
                 &Ap[(size_t)(row0 + m) * lda + k0 + kq * 8]);
        }
        if (BN == 64 || tid < 128) {
            int n = tid >> 2, kq = tid & 3;
            cp16(&smB[s][n * STR + kq * 8],
                 &Bp[(size_t)(col0 + n) * ldb + k0 + kq * 8]);
        }
        cp_commit();
    };

    load_stage(0, 0);
    load_stage(1, BK);

    if (MODE == 2) {
        int bb = row0 >> 8;
        float mv = mrow[bb * 256 + tid];
        red[tid] = mv;
        __syncthreads();
        for (int o = 128; o > 0; o >>= 1) {
            if (tid < o) red[tid] = fmaxf(red[tid], red[tid + o]);
            __syncthreads();
        }
        float M = red[0];
        __syncthreads();
        red[tid] = lrow[bb * 256 + tid] * expf(mv - M);
        __syncthreads();
        for (int o = 128; o > 0; o >>= 1) {
            if (tid < o) red[tid] += red[tid + o];
            __syncthreads();
        }
        float L = red[0];
        if (tid < BM) {
            float a_ = expf(mrow[row0 + tid] - M) / L;
            salpha[tid] = a_;
            swv[tid] = a_ * lrow[row0 + tid];
        }
        __syncthreads();
    }

    for (int it = 0; it < kiter; it++) {
        cp_wait1();
        __syncthreads();
        if (it + 2 < kiter) load_stage((it + 2) % 3, (it + 2) * BK);
        else                cp_commit();

        const __nv_bfloat16* As_ = smA[it % 3];
        const __nv_bfloat16* Bs_ = smB[it % 3];
        #pragma unroll
        for (int ks = 0; ks < BK; ks += 16) {
            unsigned a[MI][4];
            #pragma unroll
            for (int mi = 0; mi < MI; mi++) {
                int r = wm * (BM / 2) + mi * 16;
                a[mi][0] = *(const unsigned*)&As_[(r + g) * STR + ks + 2 * tg];
                a[mi][1] = *(const unsigned*)&As_[(r + 8 + g) * STR + ks + 2 * tg];
                a[mi][2] = *(const unsigned*)&As_[(r + g) * STR + ks + 8 + 2 * tg];
                a[mi][3] = *(const unsigned*)&As_[(r + 8 + g) * STR + ks + 8 + 2 * tg];
            }
            unsigned b[NI][2];
            #pragma unroll
            for (int ni = 0; ni < NI; ni++) {
                int c = wn * WN + ni * 8 + g;
                b[ni][0] = *(const unsigned*)&Bs_[c * STR + ks + 2 * tg];
                b[ni][1] = *(const unsigned*)&Bs_[c * STR + ks + 8 + 2 * tg];
            }
            #pragma unroll
            for (int mi = 0; mi < MI; mi++)
                #pragma unroll
                for (int ni = 0; ni < NI; ni++)
                    mma_bf16(acc[mi][ni], a[mi], b[ni]);
        }
        __syncthreads();
    }

    #pragma unroll
    for (int mi = 0; mi < MI; mi++) {
        #pragma unroll
        for (int ni = 0; ni < NI; ni++) {
            int r = row0 + wm * (BM / 2) + mi * 16 + g;
            int c = col0 + wn * WN + ni * 8 + tg * 2;
            float* a4 = acc[mi][ni];
            #pragma unroll
            for (int h = 0; h < 2; h++) {
                int rr = r + h * 8;
                float v0 = a4[h * 2], v1 = a4[h * 2 + 1];
                if (MODE == 0) {
                    __nv_bfloat162 p = __floats2bfloat162_rn(v0, v1);
                    *(unsigned*)&((__nv_bfloat16*)Cp)[(size_t)rr * ldc + c] =
                        *(unsigned*)&p;
                } else {
                    if (MODE == 2) {
                        float ar = salpha[rr - row0], wr = swv[rr - row0];
                        v0 = ar * v0 + wr * bocol[c]     + Xadd[(size_t)rr * ldc + c];
                        v1 = ar * v1 + wr * bocol[c + 1] + Xadd[(size_t)rr * ldc + c + 1];
                    }
                    ((float*)Cp)[(size_t)rr * ldc + c]     = v0;
                    ((float*)Cp)[(size_t)rr * ldc + c + 1] = v1;
                }
            }
        }
    }
}

// -- fused extract(bits) + qk-mma + Gu-mma, all tensor core -------------------
// sV[64][264]: natural row-major staged via cp.async (pad rows zeroed).
// qk: C = z(replicated rows) @ V^T  -> B read direct from sV (k-contiguous)
// Gu: C = es(row 0) @ V            -> B via ldmatrix.x2.trans from sV
__global__ __launch_bounds__(256) void qkg_kernel() {
    int bt = blockIdx.x, b = bt / NT;
    __shared__ __nv_bfloat16 sV[NS * 264];       // 33.8 KB
    __shared__ unsigned zb[128];                 // bf16 pairs of z
    __shared__ float qks[NS];
    __shared__ unsigned es2[NS / 2];
    __shared__ float ms_sh, c0s;
    __shared__ int sidx[NS];
    int tid = threadIdx.x;
    int w = tid >> 5, lane = tid & 31;
    int g = lane >> 2, tg = lane & 3;

    // z (bf16) + c0 from Z halves; idx extraction in parallel on warp 7
    if (tid < 128) {
        const float2* z0 = (const float2*)&g_Zh[0][(size_t)bt * NCV2];
        const float2* z1 = (const float2*)&g_Zh[1][(size_t)bt * NCV2];
        float2 pa = z0[tid], pb = z1[tid];
        __nv_bfloat162 p = __floats2bfloat162_rn(pa.x + pb.x, pa.y + pb.y);
        zb[tid] = *(unsigned*)&p;
    } else if (tid == 128) {
        c0s = g_Zh[0][(size_t)bt * NCV2 + 256] + g_Zh[1][(size_t)bt * NCV2 + 256];
    }
    if (w == 7) {
        unsigned wd = g_mbits[bt * 32 + lane];
        int cnt = __popc(wd);
        int inc = cnt;
        #pragma unroll
        for (int o = 1; o < 32; o <<= 1) {
            int nv = __shfl_up_sync(0xFFFFFFFFu, inc, o);
            if (lane >= o) inc += nv;
        }
        int base = inc - cnt;
        int total = __shfl_sync(0xFFFFFFFFu, inc, 31);
        while (wd) {
            int bp = __ffs(wd) - 1;
            if (base < NS) sidx[base] = lane * 32 + bp;
            wd &= wd - 1;
            base++;
        }
        for (int s = total + lane; s < NS; s += 32) sidx[s] = NV;
    }
    __syncthreads();
    float c0 = c0s;

    // stage vision rows: warp w owns rows s in [8w, 8w+8)
    const __nv_bfloat16* vb = g_vis16 + (size_t)b * NV * NCV;
    #pragma unroll
    for (int q = 0; q < 8; q++) {
        int s = w * 8 + q;
        int vidx = sidx[s];
        if (vidx < NV)
            cp16(&sV[s * 264 + lane * 8], &vb[(size_t)vidx * NCV + lane * 8]);
        else
            *(uint4*)&sV[s * 264 + lane * 8] = make_uint4(0, 0, 0, 0);
    }
    cp_commit();
    cp_wait0();
    __syncwarp();

    // qk via mma: warp w computes qk for its own rows [8w, 8w+8)
    {
        float cq[4] = {};
        #pragma unroll
        for (int ks = 0; ks < 16; ks++) {
            unsigned a0 = zb[8 * ks + tg];
            unsigned a2 = zb[8 * ks + 4 + tg];
            unsigned a[4] = {a0, a0, a2, a2};
            unsigned bfr[2];
            bfr[0] = *(const unsigned*)&sV[(8 * w + g) * 264 + 16 * ks + 2 * tg];
            bfr[1] = *(const unsigned*)&sV[(8 * w + g) * 264 + 16 * ks + 8 + 2 * tg];
            mma_bf16(cq, a, bfr);
        }
        if (lane < 4) {
            int s0 = 8 * w + 2 * tg;
            qks[s0]     = (sidx[s0] < NV)     ? (cq[0] + c0) * (1.f / 32.f) - 100.f
                                              : c0 * (1.f / 32.f);
            qks[s0 + 1] = (sidx[s0 + 1] < NV) ? (cq[1] + c0) * (1.f / 32.f) - 100.f
                                              : c0 * (1.f / 32.f);
        }
    }
    __syncthreads();

    // per-token softmax stats + packed es (warp 0)
    if (w == 0) {
        float q1 = qks[lane], q2 = qks[lane + 32];
        float mx = fmaxf(q1, q2);
        #pragma unroll
        for (int o = 16; o > 0; o >>= 1)
            mx = fmaxf(mx, __shfl_xor_sync(0xFFFFFFFFu, mx, o));
        float l = expf(q1 - mx) + expf(q2 - mx);
        #pragma unroll
        for (int o = 16; o > 0; o >>= 1) l += __shfl_xor_sync(0xFFFFFFFFu, l, o);
        if (lane == 0) { g_m[bt] = mx; g_l[bt] = l; ms_sh = mx; }
        float m_ = __shfl_sync(0xFFFFFFFFu, mx, 0);
        float e0 = expf(qks[2 * lane] - m_);
        float e1 = expf(qks[2 * lane + 1] - m_);
        __nv_bfloat162 p = __floats2bfloat162_rn(e0, e1);
        es2[lane] = *(unsigned*)&p;
    }
    __syncthreads();

    // Gu = es @ V via mma + ldmatrix.trans: warp handles 32 cols (n0 = w*32)
    {
        int n0 = w * 32;
        unsigned svbase = (unsigned)__cvta_generic_to_shared(sV);
        int lr = lane & 15;
        float d[4][4] = {};
        #pragma unroll
        for (int ks2 = 0; ks2 < 4; ks2++) {
            unsigned a[4];
            a[0] = (lane < 4) ? es2[8 * ks2 + tg] : 0u;
            a[1] = 0u;
            a[2] = (lane < 4) ? es2[8 * ks2 + 4 + tg] : 0u;
            a[3] = 0u;
            #pragma unroll
            for (int nt = 0; nt < 4; nt++) {
                unsigned addr = svbase +
                    ((16 * ks2 + lr) * 264 + n0 + 8 * nt) * 2;
                unsigned bfr[2];
                ldsm_x2_t(bfr[0], bfr[1], addr);
                mma_bf16(d[nt], a, bfr);
            }
        }
        if (lane < 4) {
            #pragma unroll
            for (int nt = 0; nt < 4; nt++) {
                __nv_bfloat162 p = __floats2bfloat162_rn(d[nt][0], d[nt][1]);
                *(unsigned*)&g_G16[(size_t)bt * NCV + n0 + nt * 8 + 2 * tg] =
                    *(unsigned*)&p;
            }
        }
    }
}

// ---------------- launch ----------------
extern "C" void kernel_launch(void* const* d_in, const int* in_sizes, int n_in,
                              void* d_out, int out_size) {
    const float* x      = (const float*)d_in[0];
    const float* vision = (const float*)d_in[1];
    const void*  mask   = d_in[2];
    const float* Wu     = (const float*)d_in[3];
    const float* bu     = (const float*)d_in[4];
    const float* Wk     = (const float*)d_in[5];
    const float* Wv     = (const float*)d_in[6];
    float* out = (float*)d_out;

    float *Zh;
    cudaGetSymbolAddress((void**)&Zh, g_Zh);
    __nv_bfloat16 *Wu16, *WkT16, *WvT16, *x16, *P1X16, *P2T16, *G16;
    cudaGetSymbolAddress((void**)&Wu16, g_Wu16);
    cudaGetSymbolAddress((void**)&WkT16, g_WkT16);
    cudaGetSymbolAddress((void**)&WvT16, g_WvT16);
    cudaGetSymbolAddress((void**)&x16, g_x16);
    cudaGetSymbolAddress((void**)&P1X16, g_P1X16);
    cudaGetSymbolAddress((void**)&P2T16, g_P2T16);
    cudaGetSymbolAddress((void**)&G16, g_G16);
    float *bo, *mrow, *lrow;
    cudaGetSymbolAddress((void**)&bo, g_bo);
    cudaGetSymbolAddress((void**)&mrow, g_m);
    cudaGetSymbolAddress((void**)&lrow, g_l);

    // 1) fused prep: detect + rbo + conversions + W transposes
    prep_kernel<<<4416, 256>>>(Wu, Wk, Wv, x, vision, bu, (const unsigned*)mask);
    // 2) fused P GEMMs (BM=128: 64 + 64 blocks) + bitpack (128 blocks)
    bgemm_kernel<128, 32, 0><<<256, 256>>>(
        Wu16, WvT16, WkT16, Wu16, P1X16, P2T16,
        ND / 32, ND, ND, ND, 0, nullptr, nullptr, nullptr, nullptr, mask);
    // 3) Z halves: Z = X @ P1X^T, split-K=2, BM=128
    bgemm_kernel<128, 32, 1><<<dim3(NCV2 / 32, NBT / 128, 2), 256>>>(
        x16, nullptr, P1X16, nullptr, Zh, nullptr,
        512 / 32, ND, ND, NCV2, NBT * NCV2, nullptr, nullptr, nullptr, nullptr,
        nullptr);
    // 4) fused extract + qk-mma + Gu-mma
    qkg_kernel<<<NBT, 256>>>();
    // 5) out = alpha*(Gu @ P2) + w*bo + x, BM=128
    bgemm_kernel<128, 64, 2><<<dim3(ND / 64, NBT / 128, 1), 256>>>(
        G16, nullptr, P2T16, nullptr, out, nullptr,
        NCV / 32, NCV, NCV, ND, 0, mrow, lrow, bo, x, nullptr);
}

// round 15
// speedup vs baseline: 1.1386x; 1.0087x over previous
#include <cuda_runtime.h>
#include <cuda_bf16.h>
#include <math.h>

#define NB  4
#define NT  256
#define NV  1024
#define NS  64
#define ND  1024
#define NCV 256
#define NCV2 288
#define NBT (NB*NT)

// ---------------- scratch (device globals; no allocs allowed) ----------------
__device__ __nv_bfloat16  g_Wu16[NCV*ND];
__device__ __nv_bfloat16  g_WkT16[ND*ND];     // Wk^T  (n,k) k-contiguous
__device__ __nv_bfloat16  g_WvT16[ND*ND];     // Wv^T
__device__ __nv_bfloat16  g_x16[NBT*ND];
__device__ __nv_bfloat16  g_vis16[NB*NV*NCV];
__device__ __nv_bfloat16  g_P1X16[NCV2*ND];   // rows 0..255 P1, row 256 rvec, 257..287 zero
__device__ __nv_bfloat16  g_P2T16[ND*NCV];    // P2^T (1024 rows, k=256) k-contig
__device__ __nv_bfloat16  g_G16[NBT*NCV];     // UNNORMALIZED Gu
__device__ float g_bo[ND];                    // bu @ Wv
__device__ float g_Zh[2][NBT*NCV2];           // Z split-K halves
__device__ float g_m[NBT], g_l[NBT];
__device__ unsigned g_mbits[NBT*32];          // bit-packed transposed mask
__device__ int   g_flags;

// ---------------- helpers ----------------
__device__ __forceinline__ void mma_bf16(float* c, const unsigned* a, const unsigned* b) {
    asm volatile(
        "mma.sync.aligned.m16n8k16.row.col.f32.bf16.bf16.f32 "
        "{%0,%1,%2,%3}, {%4,%5,%6,%7}, {%8,%9}, {%0,%1,%2,%3};"
        : "+f"(c[0]), "+f"(c[1]), "+f"(c[2]), "+f"(c[3])
        : "r"(a[0]), "r"(a[1]), "r"(a[2]), "r"(a[3]), "r"(b[0]), "r"(b[1]));
}
__device__ __forceinline__ void ldsm_x4(unsigned* r, unsigned addr) {
    asm volatile("ldmatrix.sync.aligned.m8n8.x4.shared.b16 {%0,%1,%2,%3}, [%4];"
                 : "=r"(r[0]), "=r"(r[1]), "=r"(r[2]), "=r"(r[3]) : "r"(addr));
}
__device__ __forceinline__ void ldsm_x2(unsigned& r0, unsigned& r1, unsigned addr) {
    asm volatile("ldmatrix.sync.aligned.m8n8.x2.shared.b16 {%0,%1}, [%2];"
                 : "=r"(r0), "=r"(r1) : "r"(addr));
}
__device__ __forceinline__ void ldsm_x2_t(unsigned& r0, unsigned& r1, unsigned addr) {
    asm volatile("ldmatrix.sync.aligned.m8n8.x2.trans.shared.b16 {%0,%1}, [%2];"
                 : "=r"(r0), "=r"(r1) : "r"(addr));
}
__device__ __forceinline__ void cp16(void* smem, const void* g) {
    unsigned s = (unsigned)__cvta_generic_to_shared(smem);
    asm volatile("cp.async.cg.shared.global [%0], [%1], 16;\n" :: "r"(s), "l"(g));
}
__device__ __forceinline__ void cp_commit() {
    asm volatile("cp.async.commit_group;\n");
}
__device__ __forceinline__ void cp_wait1() {
    asm volatile("cp.async.wait_group 1;\n");
}
__device__ __forceinline__ void cp_wait0() {
    asm volatile("cp.async.wait_group 0;\n");
}
__device__ __forceinline__ void st_bf16x4(__nv_bfloat16* p, float4 v) {
    __nv_bfloat162 lo = __floats2bfloat162_rn(v.x, v.y);
    __nv_bfloat162 hi = __floats2bfloat162_rn(v.z, v.w);
    uint2 u;
    u.x = *(unsigned*)&lo;
    u.y = *(unsigned*)&hi;
    *(uint2*)p = u;
}

// ---------------- fused prep: detect + rbo + convert + transpose-convert ----
__global__ __launch_bounds__(256) void prep_kernel(
        const float* __restrict__ Wu, const float* __restrict__ Wk,
        const float* __restrict__ Wv, const float* __restrict__ x,
        const float* __restrict__ vision, const float* __restrict__ bu,
        const unsigned* __restrict__ mask) {
    __shared__ float sh[32][33];
    int blk = blockIdx.x, tid = threadIdx.x;
    if (blk < 32) {                              // mask format detection
        int f = 0;
        for (int i = blk * 256 + tid; i < 32768; i += 32 * 256) {
            unsigned w = mask[i];
            if (w > 1u)           f |= 1;
            if (w == 0x3F800000u) f |= 2;
            if (w == 0x3F803F80u) f |= 4;
            if (w == 0x00003F80u) f |= 8;
        }
        if (f) atomicOr(&g_flags, f);
        return;
    }
    blk -= 32;
    if (blk < 32) {                              // rvec -> P1X row 256, bo = bu@Wv
        const float* W = (blk < 16) ? Wk : Wv;
        int jbase = (blk & 15) * 64;
        int jl = tid & 63, isl = tid >> 6;
        int j = jbase + jl;
        float s = 0.f;
        int i0 = isl * 256;
        #pragma unroll 8
        for (int i = 0; i < 256; i++) {
            int ii = i0 + i;
            s += bu[ii] * W[(size_t)ii * ND + j];
        }
        ((float*)sh)[tid] = s;
        __syncthreads();
        if (isl == 0) {
            float* r = (float*)sh;
            float tot = r[jl] + r[64 + jl] + r[128 + jl] + r[192 + jl];
            if (blk < 16) g_P1X16[(size_t)256 * ND + j] = __float2bfloat16(tot);
            else          g_bo[j] = tot;
        }
        return;
    }
    blk -= 32;
    if (blk < 256) {                             // Wu -> bf16
        int q = blk * 256 + tid;
        st_bf16x4(&g_Wu16[q * 4], ((const float4*)Wu)[q]);
        return;
    }
    blk -= 256;
    if (blk < 1024) {                            // x -> bf16
        int q = blk * 256 + tid;
        st_bf16x4(&g_x16[q * 4], ((const float4*)x)[q]);
        return;
    }
    blk -= 1024;
    if (blk < 1024) {                            // vision -> bf16
        int q = blk * 256 + tid;
        st_bf16x4(&g_vis16[q * 4], ((const float4*)vision)[q]);
        return;
    }
    blk -= 1024;
    {                                            // transpose-convert Wk / Wv
        int mat = blk >> 10;                     // 0 = Wk, 1 = Wv
        int tt = blk & 1023;
        int Tr = (tt >> 5) * 32, Tc = (tt & 31) * 32;
        const float* M = mat ? Wv : Wk;
        __nv_bfloat16* O = mat ? g_WvT16 : g_WkT16;
        int r = tid >> 5, c = tid & 31;
        #pragma unroll
        for (int i = 0; i < 4; i++)
            sh[r + 8 * i][c] = M[(size_t)(Tr + r + 8 * i) * ND + Tc + c];
        __syncthreads();
        int ci = tid >> 3, rp = (tid & 7) * 2;
        #pragma unroll
        for (int j = 0; j < 2; j++) {
            int ri = rp + 16 * j;
            __nv_bfloat162 p = __floats2bfloat162_rn(sh[ri][ci], sh[ri + 1][ci]);
            *(unsigned*)&O[(size_t)(Tc + ci) * ND + Tr + ri] = *(unsigned*)&p;
        }
    }
}

// ---------------- bf16 3-stage pipelined tensor GEMM (TRANSB layout) --------
// Fragments loaded via ldmatrix (x4 for A, x2 for B). STR=40 elems = 80B rows
// (16B aligned, 20-word stride -> conflict-free 8-phase LDSM).
// MODE 0: fused P GEMMs + bitpack (bid>=128), bf16 out
// MODE 1: split-K halves: z; Cp = C0 + z*csz (fp32)
// MODE 2: EPI with fused batch-softmax merge
template <int BM, int BN, int MODE>
__global__ __launch_bounds__(256) void bgemm_kernel(
        const __nv_bfloat16* __restrict__ A0,
        const __nv_bfloat16* __restrict__ A1,
        const __nv_bfloat16* __restrict__ B0,
        const __nv_bfloat16* __restrict__ B1,
        void* __restrict__ C0, void* __restrict__ C1,
        int kiter, int lda, int ldb, int ldc, int csz,
        const float* __restrict__ mrow,
        const float* __restrict__ lrow,
        const float* __restrict__ bocol,
        const float* __restrict__ Xadd,
        const void* __restrict__ mraw) {
    constexpr int BK = 32, STR = 40;
    constexpr int WN = BN / 4, NI = (WN + 7) / 8;
    constexpr int MI = BM / 32;
    __shared__ __nv_bfloat16 smA[3][BM * STR];
    __shared__ __nv_bfloat16 smB[3][BN * STR];
    __shared__ float red[(MODE == 2) ? 256 : 1];
    __shared__ float salpha[(MODE == 2) ? BM : 1];
    __shared__ float swv[(MODE == 2) ? BM : 1];

    int tid = threadIdx.x;

    const __nv_bfloat16* Ap = A0;
    const __nv_bfloat16* Bp = B0;
    void* Cp = C0;
    int row0, col0;
    if (MODE == 0) {
        int bid = blockIdx.x;
        if (bid >= 128) {                        // ---- bitpack branch ----
            int bb = bid - 128;
            int b = bb >> 5, vc = bb & 31;
            int flags = g_flags;
            int fmt = (flags & 12) ? 3 : (flags & 2) ? 2 : (flags & 1) ? 1 : 0;
            const size_t base = ((size_t)b * NV + vc * 32) * NT + tid;
            unsigned wd = 0;
            if (fmt == 0) {
                const int* p = (const int*)mraw;
                #pragma unroll
                for (int r = 0; r < 32; r++)
                    wd |= (p[base + (size_t)r * NT] != 0 ? 1u : 0u) << r;
            } else if (fmt == 1) {
                const unsigned char* p = (const unsigned char*)mraw;
                #pragma unroll
                for (int r = 0; r < 32; r++)
                    wd |= (p[base + (size_t)r * NT] != 0 ? 1u : 0u) << r;
            } else if (fmt == 2) {
                const float* p = (const float*)mraw;
                #pragma unroll
                for (int r = 0; r < 32; r++)
                    wd |= (p[base + (size_t)r * NT] != 0.0f ? 1u : 0u) << r;
            } else {
                const unsigned short* p = (const unsigned short*)mraw;
                #pragma unroll
                for (int r = 0; r < 32; r++)
                    wd |= (p[base + (size_t)r * NT] != 0 ? 1u : 0u) << r;
            }
            g_mbits[(b * NT + tid) * 32 + vc] = wd;
            return;
        }
        if (bid < 64) {
            row0 = (bid >> 5) * BM; col0 = (bid & 31) * BN;
        } else {
            Ap = A1; Bp = B1; Cp = C1;
            ldc = NCV;
            int t2 = bid - 64;
            row0 = (t2 >> 3) * BM; col0 = (t2 & 7) * BN;
        }
    } else {
        row0 = blockIdx.y * BM; col0 = blockIdx.x * BN;
        if (MODE == 1) {
            int kb = blockIdx.z * (kiter * BK);
            Ap = A0 + kb; Bp = B0 + kb;
            Cp = (float*)C0 + (size_t)blockIdx.z * csz;
        }
    }

    int warp = tid >> 5, lane = tid & 31;
    int wm = warp >> 2, wn = warp & 3;
    int g = lane >> 2, tg = lane & 3;

    float acc[MI][NI][4] = {};

    auto load_stage = [&](int s, int k0) {
        #pragma unroll
        for (int itr = 0; itr < BM / 64; itr++) {
            int e = itr * 256 + tid;
            int m = e >> 2, kq = e & 3;
            cp16(&smA[s][m * STR + kq * 8],
                 &Ap[(size_t)(row0 + m) * lda + k0 + kq * 8]);
        }
        if (BN == 64 || tid < 128) {
            int n = tid >> 2, kq = tid & 3;
            cp16(&smB[s][n * STR + kq * 8],
                 &Bp[(size_t)(col0 + n) * ldb + k0 + kq * 8]);
        }
        cp_commit();
    };

    load_stage(0, 0);
    load_stage(1, BK);

    if (MODE == 2) {
        int bb = row0 >> 8;
        float mv = mrow[bb * 256 + tid];
        red[tid] = mv;
        __syncthreads();
        for (int o = 128; o > 0; o >>= 1) {
            if (tid < o) red[tid] = fmaxf(red[tid], red[tid + o]);
            __syncthreads();
        }
        float M = red[0];
        __syncthreads();
        red[tid] = lrow[bb * 256 + tid] * expf(mv - M);
        __syncthreads();
        for (int o = 128; o > 0; o >>= 1) {
            if (tid < o) red[tid] += red[tid + o];
            __syncthreads();
        }
        float L = red[0];
        if (tid < BM) {
            float a_ = expf(mrow[row0 + tid] - M) / L;
            salpha[tid] = a_;
            swv[tid] = a_ * lrow[row0 + tid];
        }
        __syncthreads();
    }

    // ldmatrix per-thread row/k offsets
    unsigned smAb = (unsigned)__cvta_generic_to_shared(&smA[0][0]);
    unsigned smBb = (unsigned)__cvta_generic_to_shared(&smB[0][0]);
    int aRow = wm * (BM / 2) + (lane & 7) + ((lane >> 3) & 1) * 8;
    int aK   = (lane >> 4) * 8;
    int l16  = lane & 15;
    int bRow = wn * WN + (l16 & 7);
    int bK   = ((l16 >> 3) & 1) * 8;

    for (int it = 0; it < kiter; it++) {
        cp_wait1();
        __syncthreads();
        if (it + 2 < kiter) load_stage((it + 2) % 3, (it + 2) * BK);
        else                cp_commit();

        int st = it % 3;
        unsigned aBase = smAb + (st * BM * STR + aRow * STR + aK) * 2;
        unsigned bBase = smBb + (st * BN * STR + bRow * STR + bK) * 2;
        #pragma unroll
        for (int ks = 0; ks < BK; ks += 16) {
            unsigned a[MI][4];
            #pragma unroll
            for (int mi = 0; mi < MI; mi++)
                ldsm_x4(a[mi], aBase + (mi * 16 * STR + ks) * 2);
            unsigned b[NI][2];
            #pragma unroll
            for (int ni = 0; ni < NI; ni++)
                ldsm_x2(b[ni][0], b[ni][1], bBase + (ni * 8 * STR + ks) * 2);
            #pragma unroll
            for (int mi = 0; mi < MI; mi++)
                #pragma unroll
                for (int ni = 0; ni < NI; ni++)
                    mma_bf16(acc[mi][ni], a[mi], b[ni]);
        }
        __syncthreads();
    }

    #pragma unroll
    for (int mi = 0; mi < MI; mi++) {
        #pragma unroll
        for (int ni = 0; ni < NI; ni++) {
            int r = row0 + wm * (BM / 2) + mi * 16 + g;
            int c = col0 + wn * WN + ni * 8 + tg * 2;
            float* a4 = acc[mi][ni];
            #pragma unroll
            for (int h = 0; h < 2; h++) {
                int rr = r + h * 8;
                float v0 = a4[h * 2], v1 = a4[h * 2 + 1];
                if (MODE == 0) {
                    __nv_bfloat162 p = __floats2bfloat162_rn(v0, v1);
                    *(unsigned*)&((__nv_bfloat16*)Cp)[(size_t)rr * ldc + c] =
                        *(unsigned*)&p;
                } else {
                    if (MODE == 2) {
                        float ar = salpha[rr - row0], wr = swv[rr - row0];
                        v0 = ar * v0 + wr * bocol[c]     + Xadd[(size_t)rr * ldc + c];
                        v1 = ar * v1 + wr * bocol[c + 1] + Xadd[(size_t)rr * ldc + c + 1];
                    }
                    ((float*)Cp)[(size_t)rr * ldc + c]     = v0;
                    ((float*)Cp)[(size_t)rr * ldc + c + 1] = v1;
                }
            }
        }
    }
}

// -- fused extract(bits) + qk-mma + Gu-mma, all tensor core -------------------
__global__ __launch_bounds__(256) void qkg_kernel() {
    int bt = blockIdx.x, b = bt / NT;
    __shared__ __nv_bfloat16 sV[NS * 264];       // 33.8 KB
    __shared__ unsigned zb[128];                 // bf16 pairs of z
    __shared__ float qks[NS];
    __shared__ float c0s;
    __shared__ int sidx[NS];
    int tid = threadIdx.x;
    int w = tid >> 5, lane = tid & 31;
    int g = lane >> 2, tg = lane & 3;

    // z (bf16) + c0 from Z halves; idx extraction in parallel on warp 7
    if (tid < 128) {
        const float2* z0 = (const float2*)&g_Zh[0][(size_t)bt * NCV2];
        const float2* z1 = (const float2*)&g_Zh[1][(size_t)bt * NCV2];
        float2 pa = z0[tid], pb = z1[tid];
        __nv_bfloat162 p = __floats2bfloat162_rn(pa.x + pb.x, pa.y + pb.y);
        zb[tid] = *(unsigned*)&p;
    } else if (tid == 128) {
        c0s = g_Zh[0][(size_t)bt * NCV2 + 256] + g_Zh[1][(size_t)bt * NCV2 + 256];
    }
    if (w == 7) {
        unsigned wd = g_mbits[bt * 32 + lane];
        int cnt = __popc(wd);
        int inc = cnt;
        #pragma unroll
        for (int o = 1; o < 32; o <<= 1) {
            int nv = __shfl_up_sync(0xFFFFFFFFu, inc, o);
            if (lane >= o) inc += nv;
        }
        int base = inc - cnt;
        int total = __shfl_sync(0xFFFFFFFFu, inc, 31);
        while (wd) {
            int bp = __ffs(wd) - 1;
            if (base < NS) sidx[base] = lane * 32 + bp;
            wd &= wd - 1;
            base++;
        }
        for (int s = total + lane; s < NS; s += 32) sidx[s] = NV;
    }
    __syncthreads();
    float c0 = c0s;

    // stage vision rows: warp w owns rows s in [8w, 8w+8)
    const __nv_bfloat16* vb = g_vis16 + (size_t)b * NV * NCV;
    #pragma unroll
    for (int q = 0; q < 8; q++) {
        int s = w * 8 + q;
        int vidx = sidx[s];
        if (vidx < NV)
            cp16(&sV[s * 264 + lane * 8], &vb[(size_t)vidx * NCV + lane * 8]);
        else
            *(uint4*)&sV[s * 264 + lane * 8] = make_uint4(0, 0, 0, 0);
    }
    cp_commit();
    cp_wait0();
    __syncwarp();

    // qk via mma: warp w computes qk for its own rows [8w, 8w+8)
    {
        float cq[4] = {};
        #pragma unroll
        for (int ks = 0; ks < 16; ks++) {
            unsigned a0 = zb[8 * ks + tg];
            unsigned a2 = zb[8 * ks + 4 + tg];
            unsigned a[4] = {a0, a0, a2, a2};
            unsigned bfr[2];
            bfr[0] = *(const unsigned*)&sV[(8 * w + g) * 264 + 16 * ks + 2 * tg];
            bfr[1] = *(const unsigned*)&sV[(8 * w + g) * 264 + 16 * ks + 8 + 2 * tg];
            mma_bf16(cq, a, bfr);
        }
        if (lane < 4) {
            int s0 = 8 * w + 2 * tg;
            qks[s0]     = (sidx[s0] < NV)     ? (cq[0] + c0) * (1.f / 32.f) - 100.f
                                              : c0 * (1.f / 32.f);
            qks[s0 + 1] = (sidx[s0 + 1] < NV) ? (cq[1] + c0) * (1.f / 32.f) - 100.f
                                              : c0 * (1.f / 32.f);
        }
    }
    __syncthreads();

    // per-warp redundant softmax stats: each lane holds es word kp=lane
    unsigned esw;
    {
        float q1 = qks[lane], q2 = qks[lane + 32];
        float mx = fmaxf(q1, q2);
        #pragma unroll
        for (int o = 16; o > 0; o >>= 1)
            mx = fmaxf(mx, __shfl_xor_sync(0xFFFFFFFFu, mx, o));
        float l = expf(q1 - mx) + expf(q2 - mx);
        #pragma unroll
        for (int o = 16; o > 0; o >>= 1) l += __shfl_xor_sync(0xFFFFFFFFu, l, o);
        if (tid == 0) { g_m[bt] = mx; g_l[bt] = l; }
        float e0 = expf(qks[2 * lane] - mx);
        float e1 = expf(qks[2 * lane + 1] - mx);
        __nv_bfloat162 p = __floats2bfloat162_rn(e0, e1);
        esw = *(unsigned*)&p;
    }

    // Gu = es @ V via mma + ldmatrix.trans: warp handles 32 cols (n0 = w*32)
    {
        int n0 = w * 32;
        unsigned svbase = (unsigned)__cvta_generic_to_shared(sV);
        int lr = lane & 15;
        float d[4][4] = {};
        #pragma unroll
        for (int ks2 = 0; ks2 < 4; ks2++) {
            unsigned ea0 = __shfl_sync(0xFFFFFFFFu, esw, 8 * ks2 + tg);
            unsigned ea2 = __shfl_sync(0xFFFFFFFFu, esw, 8 * ks2 + 4 + tg);
            unsigned a[4];
            a[0] = (lane < 4) ? ea0 : 0u;
            a[1] = 0u;
            a[2] = (lane < 4) ? ea2 : 0u;
            a[3] = 0u;
            #pragma unroll
            for (int nt = 0; nt < 4; nt++) {
                unsigned addr = svbase +
                    ((16 * ks2 + lr) * 264 + n0 + 8 * nt) * 2;
                unsigned bfr[2];
                ldsm_x2_t(bfr[0], bfr[1], addr);
                mma_bf16(d[nt], a, bfr);
            }
        }
        if (lane < 4) {
            #pragma unroll
            for (int nt = 0; nt < 4; nt++) {
                __nv_bfloat162 p = __floats2bfloat162_rn(d[nt][0], d[nt][1]);
                *(unsigned*)&g_G16[(size_t)bt * NCV + n0 + nt * 8 + 2 * tg] =
                    *(unsigned*)&p;
            }
        }
    }
}

// ---------------- launch ----------------
extern "C" void kernel_launch(void* const* d_in, const int* in_sizes, int n_in,
                              void* d_out, int out_size) {
    const float* x      = (const float*)d_in[0];
    const float* vision = (const float*)d_in[1];
    const void*  mask   = d_in[2];
    const float* Wu     = (const float*)d_in[3];
    const float* bu     = (const float*)d_in[4];
    const float* Wk     = (const float*)d_in[5];
    const float* Wv     = (const float*)d_in[6];
    float* out = (float*)d_out;

    float *Zh;
    cudaGetSymbolAddress((void**)&Zh, g_Zh);
    __nv_bfloat16 *Wu16, *WkT16, *WvT16, *x16, *P1X16, *P2T16, *G16;
    cudaGetSymbolAddress((void**)&Wu16, g_Wu16);
    cudaGetSymbolAddress((void**)&WkT16, g_WkT16);
    cudaGetSymbolAddress((void**)&WvT16, g_WvT16);
    cudaGetSymbolAddress((void**)&x16, g_x16);
    cudaGetSymbolAddress((void**)&P1X16, g_P1X16);
    cudaGetSymbolAddress((void**)&P2T16, g_P2T16);
    cudaGetSymbolAddress((void**)&G16, g_G16);
    float *bo, *mrow, *lrow;
    cudaGetSymbolAddress((void**)&bo, g_bo);
    cudaGetSymbolAddress((void**)&mrow, g_m);
    cudaGetSymbolAddress((void**)&lrow, g_l);

    // 1) fused prep: detect + rbo + conversions + W transposes
    prep_kernel<<<4416, 256>>>(Wu, Wk, Wv, x, vision, bu, (const unsigned*)mask);
    // 2) fused P GEMMs (BM=128: 64 + 64 blocks) + bitpack (128 blocks)
    bgemm_kernel<128, 32, 0><<<256, 256>>>(
        Wu16, WvT16, WkT16, Wu16, P1X16, P2T16,
        ND / 32, ND, ND, ND, 0, nullptr, nullptr, nullptr, nullptr, mask);
    // 3) Z halves: Z = X @ P1X^T, split-K=2, BM=128
    bgemm_kernel<128, 32, 1><<<dim3(NCV2 / 32, NBT / 128, 2), 256>>>(
        x16, nullptr, P1X16, nullptr, Zh, nullptr,
        512 / 32, ND, ND, NCV2, NBT * NCV2, nullptr, nullptr, nullptr, nullptr,
        nullptr);
    // 4) fused extract + qk-mma + Gu-mma
    qkg_kernel<<<NBT, 256>>>();
    // 5) out = alpha*(Gu @ P2) + w*bo + x, BM=128
    bgemm_kernel<128, 64, 2><<<dim3(ND / 64, NBT / 128, 1), 256>>>(
        G16, nullptr, P2T16, nullptr, out, nullptr,
        NCV / 32, NCV, NCV, ND, 0, mrow, lrow, bo, x, nullptr);
}